// round 3
// baseline (speedup 1.0000x reference)
#include <cuda_runtime.h>

// Shapes (fixed):
//   x:   (176, 64, 56, 56) f32
//   y:   (176, 128, 28, 28) f32
//   out: (176, 192, 56, 56) f32 = concat(x, nearest_upsample2x(y)) on channels
namespace cfg {
constexpr int B  = 176;
constexpr int C1 = 64;
constexpr int C2 = 128;
constexpr int H1 = 56;
constexpr int W1 = 56;
constexpr int H2 = 28;

constexpr int HW1_F4       = H1 * W1 / 4;        // 784 out float4 per plane
constexpr int X_F4_PER_B   = C1 * HW1_F4;        // 50176 = 512 * 98
constexpr int OUT_F4_PER_B = (C1 + C2) * HW1_F4; // 150528
constexpr int W1_F4        = W1 / 4;             // 14
constexpr int Y_F4_PER_ROW = 7;                  // 28 floats / 4

constexpr int T = 256;

// x path: each block copies 512 float4 (2 per thread, block-strided)
constexpr int N_XCOPY = B * X_F4_PER_B;                   // 8,830,976
constexpr int XBLK    = N_XCOPY / (2 * T);                // 17,248 (exact)
constexpr int BLOCKS_PER_BATCH_X = X_F4_PER_B / (2 * T);  // 98 (exact)

// y path: one thread per y float4 = per (b, c, h2, w44)
constexpr int N_YUP = B * C2 * H2 * Y_F4_PER_ROW;         // 4,415,488
constexpr int YBLK  = N_YUP / T;                          // 17,248 (exact)
}

__global__ void __launch_bounds__(cfg::T) fused_concat_upsample(
    const float4* __restrict__ x,
    const float4* __restrict__ y4,
    float4* __restrict__ out)
{
    int bid = blockIdx.x;
    if (bid < cfg::XBLK) {
        // ---- x copy: out channels [0,64). Block never straddles a batch. ----
        int b    = bid / cfg::BLOCKS_PER_BATCH_X;
        int i0   = bid * (2 * cfg::T) + threadIdx.x;      // first float4
        // two independent, fully-coalesced loads up front (MLP)
        float4 v0 = __ldcs(&x[i0]);
        float4 v1 = __ldcs(&x[i0 + cfg::T]);
        int r0 = i0 - b * cfg::X_F4_PER_B;
        int ob = b * cfg::OUT_F4_PER_B;
        __stcs(&out[ob + r0],          v0);
        __stcs(&out[ob + r0 + cfg::T], v1);
    } else {
        // ---- y nearest-2x upsample: out channels [64,192) ----
        int i = (bid - cfg::XBLK) * cfg::T + threadIdx.x;
        // i = ((b*C2 + c)*H2 + h2)*7 + w44  — exactly the y4 index.
        float4 v = __ldcs(&y4[i]);

        int w44 = i % cfg::Y_F4_PER_ROW;
        int t   = i / cfg::Y_F4_PER_ROW;                  // (b*C2+c)*H2 + h2
        int h2  = t % cfg::H2;
        int bc  = t / cfg::H2;                            // b*C2 + c
        int c   = bc % cfg::C2;
        int b   = bc / cfg::C2;

        float4 o0, o1;
        o0.x = v.x; o0.y = v.x; o0.z = v.y; o0.w = v.y;
        o1.x = v.z; o1.y = v.z; o1.z = v.w; o1.w = v.w;

        int obase = b * cfg::OUT_F4_PER_B
                  + (cfg::C1 + c) * cfg::HW1_F4
                  + (2 * h2) * cfg::W1_F4 + 2 * w44;
        // even output row (2*h2): 32 contiguous bytes
        __stcs(&out[obase],     o0);
        __stcs(&out[obase + 1], o1);
        // odd output row (2*h2+1): same data, +14 float4
        __stcs(&out[obase + cfg::W1_F4],     o0);
        __stcs(&out[obase + cfg::W1_F4 + 1], o1);
    }
}

extern "C" void kernel_launch(void* const* d_in, const int* in_sizes, int n_in,
                              void* d_out, int out_size) {
    const float4* x  = (const float4*)d_in[0];
    const float4* y4 = (const float4*)d_in[1];
    float4* out = (float4*)d_out;

    fused_concat_upsample<<<cfg::XBLK + cfg::YBLK, cfg::T>>>(x, y4, out);
}

// round 4
// speedup vs baseline: 1.1436x; 1.1436x over previous
#include <cuda_runtime.h>

// Shapes (fixed):
//   x:   (176, 64, 56, 56) f32
//   y:   (176, 128, 28, 28) f32
//   out: (176, 192, 56, 56) f32 = concat(x, nearest_upsample2x(y)) on channels
namespace cfg {
constexpr int B  = 176;
constexpr int C1 = 64;
constexpr int C2 = 128;
constexpr int H1 = 56;
constexpr int W1 = 56;
constexpr int H2 = 28;

constexpr int HW1_F4       = H1 * W1 / 4;        // 784 out float4 per plane
constexpr int X_F4_PER_B   = C1 * HW1_F4;        // 50176 = 1024 * 49
constexpr int OUT_F4_PER_B = (C1 + C2) * HW1_F4; // 150528
constexpr int W1_F4        = W1 / 4;             // 14

constexpr int T = 256;

// x path: each block copies 1024 float4 (4 per thread, block-strided,
// loads batched up front for MLP). A block never straddles a batch:
// 50176 / 1024 = 49 exactly.
constexpr int BLOCKS_PER_BATCH_X = X_F4_PER_B / (4 * T);  // 49
constexpr int XBLK = B * BLOCKS_PER_BATCH_X;              // 8624

// y path: one thread per y float2 = per (b, c, h2, w4)  [identical to R2]
constexpr int N_YUP = B * C2 * H2 * W1_F4;                // 8,830,976
constexpr int YBLK  = N_YUP / T;                          // 34,496 (exact)
}

__global__ void __launch_bounds__(cfg::T) fused_concat_upsample(
    const float4* __restrict__ x,
    const float2* __restrict__ y2,
    float4* __restrict__ out)
{
    int bid = blockIdx.x;
    if (bid < cfg::XBLK) {
        // ---- x copy: out channels [0,64) ----
        int b  = bid / cfg::BLOCKS_PER_BATCH_X;
        int i0 = bid * (4 * cfg::T) + threadIdx.x;
        // 4 independent, fully-coalesced loads batched up front (MLP=4)
        float4 v0 = x[i0];
        float4 v1 = x[i0 + 1 * cfg::T];
        float4 v2 = x[i0 + 2 * cfg::T];
        float4 v3 = x[i0 + 3 * cfg::T];
        int o0 = b * cfg::OUT_F4_PER_B + (i0 - b * cfg::X_F4_PER_B);
        out[o0]              = v0;
        out[o0 + 1 * cfg::T] = v1;
        out[o0 + 2 * cfg::T] = v2;
        out[o0 + 3 * cfg::T] = v3;
    } else {
        // ---- y nearest-2x upsample: out channels [64,192) ----
        int i = (bid - cfg::XBLK) * cfg::T + threadIdx.x;
        // i = ((b*C2 + c)*H2 + h2)*14 + w4  — exactly the y2 index.
        float2 v = y2[i];

        int w4 = i % cfg::W1_F4;
        int t  = i / cfg::W1_F4;                          // (b*C2+c)*H2 + h2
        int h2 = t % cfg::H2;
        int bc = t / cfg::H2;                             // b*C2 + c
        int c  = bc % cfg::C2;
        int b  = bc / cfg::C2;

        float4 o;
        o.x = v.x; o.y = v.x;
        o.z = v.y; o.w = v.y;

        int obase = b * cfg::OUT_F4_PER_B
                  + (cfg::C1 + c) * cfg::HW1_F4
                  + (2 * h2) * cfg::W1_F4 + w4;
        out[obase]              = o;   // row 2*h2   (warp-contiguous)
        out[obase + cfg::W1_F4] = o;   // row 2*h2+1 (warp-contiguous)
    }
}

extern "C" void kernel_launch(void* const* d_in, const int* in_sizes, int n_in,
                              void* d_out, int out_size) {
    const float4* x  = (const float4*)d_in[0];
    const float2* y2 = (const float2*)d_in[1];
    float4* out = (float4*)d_out;

    fused_concat_upsample<<<cfg::XBLK + cfg::YBLK, cfg::T>>>(x, y2, out);
}

// round 5
// speedup vs baseline: 1.1474x; 1.0033x over previous
#include <cuda_runtime.h>

// Shapes (fixed):
//   x:   (176, 64, 56, 56) f32
//   y:   (176, 128, 28, 28) f32
//   out: (176, 192, 56, 56) f32 = concat(x, nearest_upsample2x(y)) on channels
namespace cfg {
constexpr int B  = 176;
constexpr int C1 = 64;
constexpr int C2 = 128;
constexpr int H1 = 56;
constexpr int W1 = 56;
constexpr int H2 = 28;

constexpr int HW1_F4       = H1 * W1 / 4;        // 784 out float4 per plane
constexpr int X_F4_PER_B   = C1 * HW1_F4;        // 50176 = 1024 * 49
constexpr int OUT_F4_PER_B = (C1 + C2) * HW1_F4; // 150528
constexpr int W1_F4        = W1 / 4;             // 14

constexpr int T = 256;

// x path: each block copies 1024 float4 (4 per thread, loads batched up front).
// A block never straddles a batch: 50176 / 1024 = 49 exactly.
constexpr int BLOCKS_PER_BATCH_X = X_F4_PER_B / (4 * T);  // 49
constexpr int XBLK = B * BLOCKS_PER_BATCH_X;              // 8624

// y path: each thread handles 2 y float2s (block covers 512), loads batched.
constexpr int N_YUP = B * C2 * H2 * W1_F4;                // 8,830,976 float2
constexpr int YBLK  = N_YUP / (2 * T);                    // 17,248 (exact)
}

__device__ __forceinline__ int yup_out_index(int i) {
    // i = ((b*C2 + c)*H2 + h2)*14 + w4
    int w4 = i % cfg::W1_F4;
    int t  = i / cfg::W1_F4;                // (b*C2+c)*H2 + h2
    int h2 = t % cfg::H2;
    int bc = t / cfg::H2;                   // b*C2 + c
    int c  = bc % cfg::C2;
    int b  = bc / cfg::C2;
    return b * cfg::OUT_F4_PER_B
         + (cfg::C1 + c) * cfg::HW1_F4
         + (2 * h2) * cfg::W1_F4 + w4;
}

__global__ void __launch_bounds__(cfg::T) fused_concat_upsample(
    const float4* __restrict__ x,
    const float2* __restrict__ y2,
    float4* __restrict__ out)
{
    int bid = blockIdx.x;
    if (bid < cfg::XBLK) {
        // ---- x copy: out channels [0,64) ----
        int b  = bid / cfg::BLOCKS_PER_BATCH_X;
        int i0 = bid * (4 * cfg::T) + threadIdx.x;
        float4 v0 = x[i0];
        float4 v1 = x[i0 + 1 * cfg::T];
        float4 v2 = x[i0 + 2 * cfg::T];
        float4 v3 = x[i0 + 3 * cfg::T];
        int o0 = b * cfg::OUT_F4_PER_B + (i0 - b * cfg::X_F4_PER_B);
        out[o0]              = v0;
        out[o0 + 1 * cfg::T] = v1;
        out[o0 + 2 * cfg::T] = v2;
        out[o0 + 3 * cfg::T] = v3;
    } else {
        // ---- y nearest-2x upsample: out channels [64,192) ----
        int i0 = (bid - cfg::XBLK) * (2 * cfg::T) + threadIdx.x;
        int i1 = i0 + cfg::T;
        // two independent loads batched up front (MLP=2 on the read stream)
        float2 va = y2[i0];
        float2 vb = y2[i1];

        int oa = yup_out_index(i0);
        int ob = yup_out_index(i1);

        float4 a;
        a.x = va.x; a.y = va.x; a.z = va.y; a.w = va.y;
        float4 b;
        b.x = vb.x; b.y = vb.x; b.z = vb.y; b.w = vb.y;

        out[oa]              = a;   // row 2*h2   (warp-contiguous)
        out[oa + cfg::W1_F4] = a;   // row 2*h2+1
        out[ob]              = b;
        out[ob + cfg::W1_F4] = b;
    }
}

extern "C" void kernel_launch(void* const* d_in, const int* in_sizes, int n_in,
                              void* d_out, int out_size) {
    const float4* x  = (const float4*)d_in[0];
    const float2* y2 = (const float2*)d_in[1];
    float4* out = (float4*)d_out;

    fused_concat_upsample<<<cfg::XBLK + cfg::YBLK, cfg::T>>>(x, y2, out);
}

// round 6
// speedup vs baseline: 1.1477x; 1.0003x over previous
#include <cuda_runtime.h>

// Shapes (fixed):
//   x:   (176, 64, 56, 56) f32
//   y:   (176, 128, 28, 28) f32
//   out: (176, 192, 56, 56) f32 = concat(x, nearest_upsample2x(y)) on channels
namespace cfg {
constexpr int B  = 176;
constexpr int C1 = 64;
constexpr int C2 = 128;
constexpr int H1 = 56;
constexpr int W1 = 56;
constexpr int H2 = 28;

constexpr int HW1_F4       = H1 * W1 / 4;        // 784 out float4 per plane
constexpr int X_F4_PER_B   = C1 * HW1_F4;        // 50176 = 1024 * 49
constexpr int OUT_F4_PER_B = (C1 + C2) * HW1_F4; // 150528
constexpr int W1_F4        = W1 / 4;             // 14

constexpr int T = 256;

// x path: each block copies 1024 float4 (4 per thread, loads batched up front).
// A block never straddles a batch: 50176 / 1024 = 49 exactly.
constexpr int BLOCKS_PER_BATCH_X = X_F4_PER_B / (4 * T);  // 49
constexpr int XBLK = B * BLOCKS_PER_BATCH_X;              // 8624

// y path: each thread handles 2 y float2s (block covers 512), loads batched.
constexpr int N_YUP = B * C2 * H2 * W1_F4;                // 8,830,976 float2
constexpr int YBLK  = N_YUP / (2 * T);                    // 17,248 = 2 * XBLK

// Interleave 1 x-block per 2 y-blocks so every wave carries the global
// read/write mix (smoother DRAM bus utilization, no pure-phase waves).
constexpr int NBLK = XBLK + YBLK;                         // 25,872
}

__device__ __forceinline__ int yup_out_index(int i) {
    // i = ((b*C2 + c)*H2 + h2)*14 + w4
    int w4 = i % cfg::W1_F4;
    int t  = i / cfg::W1_F4;                // (b*C2+c)*H2 + h2
    int h2 = t % cfg::H2;
    int bc = t / cfg::H2;                   // b*C2 + c
    int c  = bc % cfg::C2;
    int b  = bc / cfg::C2;
    return b * cfg::OUT_F4_PER_B
         + (cfg::C1 + c) * cfg::HW1_F4
         + (2 * h2) * cfg::W1_F4 + w4;
}

__global__ void __launch_bounds__(cfg::T) fused_concat_upsample(
    const float4* __restrict__ x,
    const float2* __restrict__ y2,
    float4* __restrict__ out)
{
    int bid = blockIdx.x;
    int grp = bid / 3;
    int lane = bid - 3 * grp;               // 0,1,2
    if (lane == 0) {
        // ---- x copy block #grp: out channels [0,64) ----
        int xb = grp;
        int b  = xb / cfg::BLOCKS_PER_BATCH_X;
        int i0 = xb * (4 * cfg::T) + threadIdx.x;
        float4 v0 = x[i0];
        float4 v1 = x[i0 + 1 * cfg::T];
        float4 v2 = x[i0 + 2 * cfg::T];
        float4 v3 = x[i0 + 3 * cfg::T];
        int o0 = b * cfg::OUT_F4_PER_B + (i0 - b * cfg::X_F4_PER_B);
        out[o0]              = v0;
        out[o0 + 1 * cfg::T] = v1;
        out[o0 + 2 * cfg::T] = v2;
        out[o0 + 3 * cfg::T] = v3;
    } else {
        // ---- y nearest-2x upsample block #(2*grp + lane-1) ----
        int yb = 2 * grp + (lane - 1);
        int i0 = yb * (2 * cfg::T) + threadIdx.x;
        int i1 = i0 + cfg::T;
        // two independent loads batched up front (MLP=2 on the read stream)
        float2 va = y2[i0];
        float2 vb = y2[i1];

        int oa = yup_out_index(i0);
        int ob = yup_out_index(i1);

        float4 a;
        a.x = va.x; a.y = va.x; a.z = va.y; a.w = va.y;
        float4 b;
        b.x = vb.x; b.y = vb.x; b.z = vb.y; b.w = vb.y;

        out[oa]              = a;   // row 2*h2   (warp-contiguous)
        out[oa + cfg::W1_F4] = a;   // row 2*h2+1
        out[ob]              = b;
        out[ob + cfg::W1_F4] = b;
    }
}

extern "C" void kernel_launch(void* const* d_in, const int* in_sizes, int n_in,
                              void* d_out, int out_size) {
    const float4* x  = (const float4*)d_in[0];
    const float2* y2 = (const float2*)d_in[1];
    float4* out = (float4*)d_out;

    fused_concat_upsample<<<cfg::NBLK, cfg::T>>>(x, y2, out);
}

// round 7
// speedup vs baseline: 1.1485x; 1.0007x over previous
#include <cuda_runtime.h>

// Shapes (fixed):
//   x:   (176, 64, 56, 56) f32
//   y:   (176, 128, 28, 28) f32
//   out: (176, 192, 56, 56) f32 = concat(x, nearest_upsample2x(y)) on channels
namespace cfg {
constexpr int B  = 176;
constexpr int C1 = 64;
constexpr int C2 = 128;
constexpr int H1 = 56;
constexpr int W1 = 56;
constexpr int H2 = 28;

constexpr int HW1_F4       = H1 * W1 / 4;        // 784 out float4 per plane
constexpr int X_F4_PER_B   = C1 * HW1_F4;        // 50176 = 1024 * 49
constexpr int OUT_F4_PER_B = (C1 + C2) * HW1_F4; // 150528
constexpr int W1_F4        = W1 / 4;             // 14

constexpr int T = 256;

// x path: each block copies 1024 float4 (4 per thread, loads batched up front).
// A block never straddles a batch: 50176 / 1024 = 49 exactly.
constexpr int BLOCKS_PER_BATCH_X = X_F4_PER_B / (4 * T);  // 49
constexpr int XBLK = B * BLOCKS_PER_BATCH_X;              // 8624

// y path: each thread handles 2 y float2s (block covers 512), loads batched.
constexpr int N_YUP = B * C2 * H2 * W1_F4;                // 8,830,976 float2
constexpr int YBLK  = N_YUP / (2 * T);                    // 17,248 (exact)
}

__device__ __forceinline__ int yup_out_index(int i) {
    // i = ((b*C2 + c)*H2 + h2)*14 + w4
    int w4 = i % cfg::W1_F4;
    int t  = i / cfg::W1_F4;                // (b*C2+c)*H2 + h2
    int h2 = t % cfg::H2;
    int bc = t / cfg::H2;                   // b*C2 + c
    int c  = bc % cfg::C2;
    int b  = bc / cfg::C2;
    return b * cfg::OUT_F4_PER_B
         + (cfg::C1 + c) * cfg::HW1_F4
         + (2 * h2) * cfg::W1_F4 + w4;
}

__global__ void __launch_bounds__(cfg::T) fused_concat_upsample(
    const float4* __restrict__ x,
    const float2* __restrict__ y2,
    float4* __restrict__ out)
{
    int bid = blockIdx.x;
    if (bid < cfg::XBLK) {
        // ---- x copy: out channels [0,64) ----
        int b  = bid / cfg::BLOCKS_PER_BATCH_X;
        int i0 = bid * (4 * cfg::T) + threadIdx.x;
        float4 v0 = x[i0];
        float4 v1 = x[i0 + 1 * cfg::T];
        float4 v2 = x[i0 + 2 * cfg::T];
        float4 v3 = x[i0 + 3 * cfg::T];
        int o0 = b * cfg::OUT_F4_PER_B + (i0 - b * cfg::X_F4_PER_B);
        __stcs(&out[o0],              v0);   // write-once: evict-first
        __stcs(&out[o0 + 1 * cfg::T], v1);
        __stcs(&out[o0 + 2 * cfg::T], v2);
        __stcs(&out[o0 + 3 * cfg::T], v3);
    } else {
        // ---- y nearest-2x upsample: out channels [64,192) ----
        int i0 = (bid - cfg::XBLK) * (2 * cfg::T) + threadIdx.x;
        int i1 = i0 + cfg::T;
        // two independent loads batched up front (MLP=2 on the read stream)
        float2 va = y2[i0];
        float2 vb = y2[i1];

        int oa = yup_out_index(i0);
        int ob = yup_out_index(i1);

        float4 a;
        a.x = va.x; a.y = va.x; a.z = va.y; a.w = va.y;
        float4 b;
        b.x = vb.x; b.y = vb.x; b.z = vb.y; b.w = vb.y;

        __stcs(&out[oa],              a);   // row 2*h2   (warp-contiguous)
        __stcs(&out[oa + cfg::W1_F4], a);   // row 2*h2+1
        __stcs(&out[ob],              b);
        __stcs(&out[ob + cfg::W1_F4], b);
    }
}

extern "C" void kernel_launch(void* const* d_in, const int* in_sizes, int n_in,
                              void* d_out, int out_size) {
    const float4* x  = (const float4*)d_in[0];
    const float2* y2 = (const float2*)d_in[1];
    float4* out = (float4*)d_out;

    fused_concat_upsample<<<cfg::XBLK + cfg::YBLK, cfg::T>>>(x, y2, out);
}